// round 16
// baseline (speedup 1.0000x reference)
#include <cuda_runtime.h>
#include <cuda_bf16.h>
#include <cstdint>

#define Dd 128
#define Bb 4096
#define NT 32            // samples per CTA
#define NTHREADS 512     // 16 warps: 8 row-strips x 2 sample-halves; 4 warps/SMSP
#define KTERMS 6         // measured term decay ~8x/term -> truncation ~4e-5 vs 1e-3
#define PW  136          // V operand pitch in u32 words

// ---- shared memory: ONLY the operand double-buffer (35 KB) ----
#define OFF_VC0 0                          // B operand buf0    17408 B
#define OFF_VC1 17408                      // B operand buf1    17408 B
#define SMEM_TOTAL 34816
// V operand layout (verified R7-R15): u32 word[s*PW + j] (j even) = (vhi[j], vhi[j+1]),
//                                     word[s*PW + j + 1]          = (vlo[j], vlo[j+1]).
// Sample halves (s 0-15 vs 16-31) are disjoint rows -> independent sync domains.

static __device__ __forceinline__ uint32_t smem_u32(const void* p) {
    uint32_t a;
    asm("{ .reg .u64 t; cvta.to.shared.u64 t, %1; cvt.u32.u64 %0, t; }" : "=r"(a) : "l"(p));
    return a;
}
static __device__ __forceinline__ void bar_half(int id) {
    asm volatile("bar.sync %0, 256;" :: "r"(id) : "memory");
}
static __device__ __forceinline__ void mma16816(float* c, const uint32_t* a,
                                                uint32_t b0, uint32_t b1) {
    asm("mma.sync.aligned.m16n8k16.row.col.f32.bf16.bf16.f32 "
        "{%0,%1,%2,%3}, {%4,%5,%6,%7}, {%8,%9}, {%0,%1,%2,%3};"
        : "+f"(c[0]), "+f"(c[1]), "+f"(c[2]), "+f"(c[3])
        : "r"(a[0]), "r"(a[1]), "r"(a[2]), "r"(a[3]), "r"(b0), "r"(b1));
}
static __device__ __forceinline__ uint16_t bf16_hi(float v) {
    uint16_t h; asm("cvt.rn.bf16.f32 %0, %1;" : "=h"(h) : "f"(v)); return h;
}
static __device__ __forceinline__ void split2(float v, uint16_t& h, uint16_t& l) {
    h = bf16_hi(v);
    float rem = v - __uint_as_float((uint32_t)h << 16);
    l = bf16_hi(rem);
}
static __device__ __forceinline__ uint32_t pkh(uint16_t a, uint16_t b) {
    return (uint32_t)a | ((uint32_t)b << 16);
}

// y_b = exp(t_b W) x_b + bias t_b ; ljd = diag(W) t_b.
// Taylor v_k = (t_b/k) W v_{k-1} on tensor cores (bf16 hi/lo error split,
// W fragments register-resident). R15 skeleton with the fixed-cost trimmed:
// fragments built straight from global W (L1/L2 broadcast across the 128
// CTAs), x/t read direct, zero full __syncthreads, smem = operand buffers.
__global__ void __launch_bounds__(NTHREADS, 1) affexp_mma_kernel(
    const float* __restrict__ x, const float* __restrict__ t,
    const float* __restrict__ W, const float* __restrict__ bias,
    float* __restrict__ out)
{
    extern __shared__ char smc[];

    const int tid = threadIdx.x;
    const int w    = tid >> 5;
    const int l    = tid & 31;
    const int g    = l >> 2;        // rows m0+g, m0+g+8 / B sample-within-8 g
    const int tq   = l & 3;         // k pairs / C cols 2tq, 2tq+1
    const int m0   = (w >> 1) * 16; // row strip
    const int half = w & 1;         // sample half = independent sync domain
    const int nbas = half * 16;
    const int hid  = (w >> 1) * 32 + l;  // dense 0..255 index WITHIN this half
    const int s0   = blockIdx.x * NT;

    // ---- A fragments (W hi/lo) straight from global, 8 k-tiles ----
    uint32_t Ahi[8][4], Alo[8][4];
    #pragma unroll
    for (int kt = 0; kt < 8; kt++) {
        int k0 = kt * 16;
        #pragma unroll
        for (int rr = 0; rr < 2; rr++) {
            int r = m0 + g + 8 * rr;
            #pragma unroll
            for (int kh = 0; kh < 2; kh++) {
                float2 p = *(const float2*)&W[(size_t)r * Dd + k0 + 2 * tq + 8 * kh];
                uint16_t h0, l0, h1, l1;
                split2(p.x, h0, l0);
                split2(p.y, h1, l1);
                Ahi[kt][2 * kh + rr] = pkh(h0, h1);
                Alo[kt][2 * kh + rr] = pkh(l0, l1);
            }
        }
    }

    // ---- y init = v0 = x in C-fragment layout; t per column (global reads) ----
    float y[8], tc[4];
    #pragma unroll
    for (int nt = 0; nt < 2; nt++) {
        int n0 = nbas + 8 * nt;
        tc[nt * 2 + 0] = t[s0 + n0 + 2 * tq];
        tc[nt * 2 + 1] = t[s0 + n0 + 2 * tq + 1];
        y[nt * 4 + 0] = x[(size_t)(s0 + n0 + 2 * tq) * Dd + m0 + g];
        y[nt * 4 + 1] = x[(size_t)(s0 + n0 + 2 * tq + 1) * Dd + m0 + g];
        y[nt * 4 + 2] = x[(size_t)(s0 + n0 + 2 * tq) * Dd + m0 + g + 8];
        y[nt * 4 + 3] = x[(size_t)(s0 + n0 + 2 * tq + 1) * Dd + m0 + g + 8];
    }

    // ---- v0 -> operand buffer 0: dense per-half index (proven R11 pattern),
    //      source = global x (coalesced 128-float rows per 16 lanes) ----
    for (int idx = hid; idx < (NT / 2) * Dd; idx += 256) {
        int s = nbas + (idx >> 7), d = idx & 127;
        uint16_t h, lo16;
        split2(x[(size_t)(s0 + s) * Dd + d], h, lo16);
        char* row = smc + OFF_VC0 + s * (PW * 4);
        int jp = d & ~1, hw = d & 1;
        *(uint16_t*)(row + jp * 4 + hw * 2)     = h;
        *(uint16_t*)(row + jp * 4 + 4 + hw * 2) = lo16;
    }
    bar_half(half + 1);

    const uint32_t vc0 = smem_u32(smc + OFF_VC0);
    const uint32_t vc1 = smem_u32(smc + OFF_VC1);

    #pragma unroll 1
    for (int k = 1; k <= KTERMS; k++) {
        const uint32_t vcur = (k & 1) ? vc0 : vc1;
        const uint32_t vnxt = (k & 1) ? vc1 : vc0;

        float C[8];
        #pragma unroll
        for (int c = 0; c < 8; c++) C[c] = 0.0f;

        #pragma unroll
        for (int kt = 0; kt < 8; kt++) {
            int k0 = kt * 16;
            #pragma unroll
            for (int nt = 0; nt < 2; nt++) {
                uint32_t rb = vcur + ((nbas + 8 * nt + g) * PW + k0 + 2 * tq) * 4;
                uint32_t bh0, bl0, bh1, bl1;
                asm("ld.shared.v2.b32 {%0,%1}, [%2];"      : "=r"(bh0), "=r"(bl0) : "r"(rb));
                asm("ld.shared.v2.b32 {%0,%1}, [%2 + 32];" : "=r"(bh1), "=r"(bl1) : "r"(rb));
                mma16816(&C[nt * 4], Ahi[kt], bh0, bh1);
                mma16816(&C[nt * 4], Alo[kt], bh0, bh1);
                mma16816(&C[nt * 4], Ahi[kt], bl0, bl1);
            }
        }

        // v = (t/k) u ; y += v ; re-split as next B operand (own half only).
        float invk = 1.0f / (float)k;
        if (k < KTERMS) {
            #pragma unroll
            for (int nt = 0; nt < 2; nt++) {
                float sc0 = tc[nt * 2] * invk, sc1 = tc[nt * 2 + 1] * invk;
                #pragma unroll
                for (int c = 0; c < 4; c++) {
                    float v = C[nt * 4 + c] * ((c & 1) ? sc1 : sc0);
                    y[nt * 4 + c] += v;
                    int s = nbas + 8 * nt + 2 * tq + (c & 1);
                    int d = m0 + g + 8 * (c >> 1);
                    uint16_t h, lo16;
                    split2(v, h, lo16);
                    uint32_t row = vnxt + s * (PW * 4);
                    int jp = d & ~1, hw = d & 1;
                    asm volatile("st.shared.b16 [%0], %1;" :: "r"(row + jp * 4 + hw * 2), "h"(h) : "memory");
                    asm volatile("st.shared.b16 [%0], %1;" :: "r"(row + jp * 4 + 4 + hw * 2), "h"(lo16) : "memory");
                }
            }
            bar_half(half + 1);   // sync ONLY this half's 8 warps
        } else {
            #pragma unroll
            for (int nt = 0; nt < 2; nt++) {
                float sc0 = tc[nt * 2] * invk, sc1 = tc[nt * 2 + 1] * invk;
                #pragma unroll
                for (int c = 0; c < 4; c++)
                    y[nt * 4 + c] += C[nt * 4 + c] * ((c & 1) ? sc1 : sc0);
            }
        }
    }

    // ---- epilogue: out = [y + bias*t | diag(W)*t], each [B, D] ----
    float b0 = bias[m0 + g], b1 = bias[m0 + g + 8];
    #pragma unroll
    for (int nt = 0; nt < 2; nt++) {
        #pragma unroll
        for (int c = 0; c < 4; c++) {
            int sG = s0 + nbas + 8 * nt + 2 * tq + (c & 1);
            int d  = m0 + g + 8 * (c >> 1);
            float bb = (c >> 1) ? b1 : b0;
            out[(size_t)sG * Dd + d] = y[nt * 4 + c] + bb * tc[nt * 2 + (c & 1)];
        }
    }
    for (int idx = tid; idx < NT * Dd; idx += NTHREADS) {
        int s = idx >> 7, d = idx & 127;
        out[(size_t)Bb * Dd + (size_t)(s0 + s) * Dd + d] = W[d * (Dd + 1)] * t[s0 + s];
    }
}

extern "C" void kernel_launch(void* const* d_in, const int* in_sizes, int n_in,
                              void* d_out, int out_size) {
    const float* x    = (const float*)d_in[0];
    const float* t    = (const float*)d_in[1];
    const float* W    = (const float*)d_in[2];
    const float* bias = (const float*)d_in[3];
    float* out = (float*)d_out;

    cudaFuncSetAttribute(affexp_mma_kernel,
                         cudaFuncAttributeMaxDynamicSharedMemorySize, SMEM_TOTAL);
    affexp_mma_kernel<<<Bb / NT, NTHREADS, SMEM_TOTAL>>>(x, t, W, bias, out);
}

// round 17
// speedup vs baseline: 1.1994x; 1.1994x over previous
#include <cuda_runtime.h>
#include <cuda_bf16.h>
#include <cstdint>

#define Dd 128
#define Bb 4096
#define NT 32            // samples per CTA
#define NTHREADS 512     // 16 warps: 8 row-strips x 2 sample-halves; 4 warps/SMSP
#define KTERMS 6         // truncation 4.8e-5 (measured R16) vs 1e-3 threshold
#define WFP 132          // Wf f32 pitch
#define XFP 132
#define PW  136          // V operand pitch in u32 words

// ---- shared memory byte offsets ----
#define OFF_WF  0                         // W f32 staging        67584 B
#define OFF_XF  (OFF_WF + 128*WFP*4)      // x tile f32           16896 B
#define OFF_TS  (OFF_XF + 32*XFP*4)       // t values               128 B
#define OFF_WD  (OFF_TS + 128)            // diag(W)                512 B
#define OFF_VC0 (OFF_WD + 512)            // V operand buf0       17408 B
#define OFF_VC1 (OFF_VC0 + 32*PW*4)       // V operand buf1       17408 B
#define SMEM_TOTAL (OFF_VC1 + 32*PW*4)    // 119936 B
// V operand layout (verified R7-R16): u32 word[s*PW + j] (j even) = (vhi[j], vhi[j+1]),
//                                     word[s*PW + j + 1]          = (vlo[j], vlo[j+1]).
// Sample halves (s 0-15 vs 16-31) are disjoint rows -> independent sync domains.

static __device__ __forceinline__ uint32_t smem_u32(const void* p) {
    uint32_t a;
    asm("{ .reg .u64 t; cvta.to.shared.u64 t, %1; cvt.u32.u64 %0, t; }" : "=r"(a) : "l"(p));
    return a;
}
static __device__ __forceinline__ void bar_half(int id) {
    asm volatile("bar.sync %0, 256;" :: "r"(id) : "memory");
}
static __device__ __forceinline__ void mma16816(float* c, const uint32_t* a,
                                                uint32_t b0, uint32_t b1) {
    asm("mma.sync.aligned.m16n8k16.row.col.f32.bf16.bf16.f32 "
        "{%0,%1,%2,%3}, {%4,%5,%6,%7}, {%8,%9}, {%0,%1,%2,%3};"
        : "+f"(c[0]), "+f"(c[1]), "+f"(c[2]), "+f"(c[3])
        : "r"(a[0]), "r"(a[1]), "r"(a[2]), "r"(a[3]), "r"(b0), "r"(b1));
}
static __device__ __forceinline__ uint16_t bf16_hi(float v) {
    uint16_t h; asm("cvt.rn.bf16.f32 %0, %1;" : "=h"(h) : "f"(v)); return h;
}
static __device__ __forceinline__ void split2(float v, uint16_t& h, uint16_t& l) {
    h = bf16_hi(v);
    float rem = v - __uint_as_float((uint32_t)h << 16);
    l = bf16_hi(rem);
}
static __device__ __forceinline__ uint32_t pkh(uint16_t a, uint16_t b) {
    return (uint32_t)a | ((uint32_t)b << 16);
}

// y_b = exp(t_b W) x_b + bias t_b ; ljd = diag(W) t_b.
// Taylor v_k = (t_b/k) W v_{k-1} on tensor cores (bf16 hi/lo error split,
// W fragments register-resident). Exactly the proven R15 kernel (coalesced
// smem staging prologue) with ONLY KTERMS 7->6 applied.
__global__ void __launch_bounds__(NTHREADS, 1) affexp_mma_kernel(
    const float* __restrict__ x, const float* __restrict__ t,
    const float* __restrict__ W, const float* __restrict__ bias,
    float* __restrict__ out)
{
    extern __shared__ char smc[];
    float* Wf = (float*)(smc + OFF_WF);
    float* Xf = (float*)(smc + OFF_XF);
    float* ts = (float*)(smc + OFF_TS);
    float* wd = (float*)(smc + OFF_WD);

    const int tid = threadIdx.x;
    const int w    = tid >> 5;
    const int l    = tid & 31;
    const int g    = l >> 2;        // rows m0+g, m0+g+8 / B sample-within-8 g
    const int tq   = l & 3;         // k pairs / C cols 2tq, 2tq+1
    const int m0   = (w >> 1) * 16; // row strip
    const int half = w & 1;         // sample half = independent sync domain
    const int nbas = half * 16;
    const int hid  = (w >> 1) * 32 + l;  // dense 0..255 index WITHIN this half
    const int s0   = blockIdx.x * NT;

    // ---- prologue: stage W, x, t in smem (coalesced) ----
    for (int idx = tid; idx < Dd * Dd; idx += NTHREADS) {
        int i = idx >> 7, j = idx & 127;
        Wf[i * WFP + j] = W[idx];
    }
    for (int idx = tid; idx < NT * Dd; idx += NTHREADS) {
        int s = idx >> 7, d = idx & 127;
        Xf[s * XFP + d] = x[(size_t)(s0 + s) * Dd + d];
    }
    if (tid < NT) ts[tid] = t[s0 + tid];
    __syncthreads();
    if (tid < Dd) wd[tid] = Wf[tid * WFP + tid];

    // ---- A fragments (W hi/lo) in registers, 8 k-tiles ----
    uint32_t Ahi[8][4], Alo[8][4];
    #pragma unroll
    for (int kt = 0; kt < 8; kt++) {
        int k0 = kt * 16;
        #pragma unroll
        for (int rr = 0; rr < 2; rr++) {
            int r = m0 + g + 8 * rr;
            #pragma unroll
            for (int kh = 0; kh < 2; kh++) {
                float2 p = *(const float2*)&Wf[r * WFP + k0 + 2 * tq + 8 * kh];
                uint16_t h0, l0, h1, l1;
                split2(p.x, h0, l0);
                split2(p.y, h1, l1);
                Ahi[kt][2 * kh + rr] = pkh(h0, h1);
                Alo[kt][2 * kh + rr] = pkh(l0, l1);
            }
        }
    }

    // ---- y init = v0 = x in C-fragment layout; t per column ----
    float y[8], tc[4];
    #pragma unroll
    for (int nt = 0; nt < 2; nt++) {
        int n0 = nbas + 8 * nt;
        tc[nt * 2 + 0] = ts[n0 + 2 * tq];
        tc[nt * 2 + 1] = ts[n0 + 2 * tq + 1];
        y[nt * 4 + 0] = Xf[(n0 + 2 * tq) * XFP + m0 + g];
        y[nt * 4 + 1] = Xf[(n0 + 2 * tq + 1) * XFP + m0 + g];
        y[nt * 4 + 2] = Xf[(n0 + 2 * tq) * XFP + m0 + g + 8];
        y[nt * 4 + 3] = Xf[(n0 + 2 * tq + 1) * XFP + m0 + g + 8];
    }

    // ---- v0 -> operand buffer 0: dense per-half index (R10 fix) ----
    for (int idx = hid; idx < (NT / 2) * Dd; idx += 256) {
        int s = nbas + (idx >> 7), d = idx & 127;
        uint16_t h, lo16;
        split2(Xf[s * XFP + d], h, lo16);
        char* row = smc + OFF_VC0 + s * (PW * 4);
        int jp = d & ~1, hw = d & 1;
        *(uint16_t*)(row + jp * 4 + hw * 2)     = h;
        *(uint16_t*)(row + jp * 4 + 4 + hw * 2) = lo16;
    }
    bar_half(half + 1);

    const uint32_t vc0 = smem_u32(smc + OFF_VC0);
    const uint32_t vc1 = smem_u32(smc + OFF_VC1);

    #pragma unroll 1
    for (int k = 1; k <= KTERMS; k++) {
        const uint32_t vcur = (k & 1) ? vc0 : vc1;
        const uint32_t vnxt = (k & 1) ? vc1 : vc0;

        float C[8];
        #pragma unroll
        for (int c = 0; c < 8; c++) C[c] = 0.0f;

        #pragma unroll
        for (int kt = 0; kt < 8; kt++) {
            int k0 = kt * 16;
            #pragma unroll
            for (int nt = 0; nt < 2; nt++) {
                uint32_t rb = vcur + ((nbas + 8 * nt + g) * PW + k0 + 2 * tq) * 4;
                uint32_t bh0, bl0, bh1, bl1;
                asm("ld.shared.v2.b32 {%0,%1}, [%2];"      : "=r"(bh0), "=r"(bl0) : "r"(rb));
                asm("ld.shared.v2.b32 {%0,%1}, [%2 + 32];" : "=r"(bh1), "=r"(bl1) : "r"(rb));
                mma16816(&C[nt * 4], Ahi[kt], bh0, bh1);
                mma16816(&C[nt * 4], Alo[kt], bh0, bh1);
                mma16816(&C[nt * 4], Ahi[kt], bl0, bl1);
            }
        }

        // v = (t/k) u ; y += v ; re-split as next B operand (own half only).
        float invk = 1.0f / (float)k;
        if (k < KTERMS) {
            #pragma unroll
            for (int nt = 0; nt < 2; nt++) {
                float sc0 = tc[nt * 2] * invk, sc1 = tc[nt * 2 + 1] * invk;
                #pragma unroll
                for (int c = 0; c < 4; c++) {
                    float v = C[nt * 4 + c] * ((c & 1) ? sc1 : sc0);
                    y[nt * 4 + c] += v;
                    int s = nbas + 8 * nt + 2 * tq + (c & 1);
                    int d = m0 + g + 8 * (c >> 1);
                    uint16_t h, lo16;
                    split2(v, h, lo16);
                    uint32_t row = vnxt + s * (PW * 4);
                    int jp = d & ~1, hw = d & 1;
                    asm volatile("st.shared.b16 [%0], %1;" :: "r"(row + jp * 4 + hw * 2), "h"(h) : "memory");
                    asm volatile("st.shared.b16 [%0], %1;" :: "r"(row + jp * 4 + 4 + hw * 2), "h"(lo16) : "memory");
                }
            }
            bar_half(half + 1);   // sync ONLY this half's 8 warps
        } else {
            #pragma unroll
            for (int nt = 0; nt < 2; nt++) {
                float sc0 = tc[nt * 2] * invk, sc1 = tc[nt * 2 + 1] * invk;
                #pragma unroll
                for (int c = 0; c < 4; c++)
                    y[nt * 4 + c] += C[nt * 4 + c] * ((c & 1) ? sc1 : sc0);
            }
        }
    }

    // ---- epilogue: out = [y + bias*t | diag(W)*t], each [B, D] ----
    float b0 = bias[m0 + g], b1 = bias[m0 + g + 8];
    #pragma unroll
    for (int nt = 0; nt < 2; nt++) {
        #pragma unroll
        for (int c = 0; c < 4; c++) {
            int sG = s0 + nbas + 8 * nt + 2 * tq + (c & 1);
            int d  = m0 + g + 8 * (c >> 1);
            float bb = (c >> 1) ? b1 : b0;
            out[(size_t)sG * Dd + d] = y[nt * 4 + c] + bb * tc[nt * 2 + (c & 1)];
        }
    }
    for (int idx = tid; idx < NT * Dd; idx += NTHREADS) {
        int s = idx >> 7, d = idx & 127;
        out[(size_t)Bb * Dd + (size_t)(s0 + s) * Dd + d] = wd[d] * ts[s];
    }
}

extern "C" void kernel_launch(void* const* d_in, const int* in_sizes, int n_in,
                              void* d_out, int out_size) {
    const float* x    = (const float*)d_in[0];
    const float* t    = (const float*)d_in[1];
    const float* W    = (const float*)d_in[2];
    const float* bias = (const float*)d_in[3];
    float* out = (float*)d_out;

    cudaFuncSetAttribute(affexp_mma_kernel,
                         cudaFuncAttributeMaxDynamicSharedMemorySize, SMEM_TOTAL);
    affexp_mma_kernel<<<Bb / NT, NTHREADS, SMEM_TOTAL>>>(x, t, W, bias, out);
}